// round 1
// baseline (speedup 1.0000x reference)
#include <cuda_runtime.h>

// Radix-select threshold + mask kernel for top-k binary mask.
// Order-preserving key: neg -> ~bits, pos -> bits | 0x80000000 (ascending).

#define CAND_CAP (1u << 24)   // 16M candidate slots (64 MB) -- selected 12-bit bin
                              // holds ~0.7M elements for N(0,1) data; huge margin.

static __device__ unsigned g_hist1[4096];
static __device__ unsigned g_hist2[4096];
static __device__ unsigned g_hist3[256];
static __device__ unsigned g_sel1, g_rank1, g_sel2, g_rank2, g_count;
static __device__ float    g_threshold;
static __device__ unsigned g_cand[CAND_CAP];

__device__ __forceinline__ unsigned f2key(float f) {
    unsigned u = __float_as_uint(f);
    return (u & 0x80000000u) ? ~u : (u | 0x80000000u);
}

__global__ void k_zero() {
    int t = blockIdx.x * blockDim.x + threadIdx.x;
    if (t < 4096) { g_hist1[t] = 0u; g_hist2[t] = 0u; }
    if (t < 256) g_hist3[t] = 0u;
    if (t == 0) g_count = 0u;
}

// Pass 1: histogram of top 12 key bits. Shared privatized (2 copies) +
// warp match-aggregation (input is concentrated into few hundred bins).
__global__ void k_hist1(const float* __restrict__ x, int n) {
    __shared__ unsigned sh[2 * 4096];
    for (int i = threadIdx.x; i < 2 * 4096; i += blockDim.x) sh[i] = 0u;
    __syncthreads();
    const unsigned copy = ((threadIdx.x >> 5) & 1u) * 4096u;
    const int lane = threadIdx.x & 31;
    const float4* x4 = (const float4*)x;
    const int n4 = n >> 2;
    const int stride = gridDim.x * blockDim.x;
    for (int i = blockIdx.x * blockDim.x + threadIdx.x; i < n4; i += stride) {
        float4 v = x4[i];
        float f[4] = {v.x, v.y, v.z, v.w};
#pragma unroll
        for (int c = 0; c < 4; c++) {
            unsigned bin = f2key(f[c]) >> 20;
            unsigned am = __activemask();
            unsigned m = __match_any_sync(am, bin);
            if (lane == __ffs(m) - 1)
                atomicAdd(&sh[copy + bin], (unsigned)__popc(m));
        }
    }
    for (int i = (n & ~3) + blockIdx.x * blockDim.x + threadIdx.x; i < n; i += stride)
        atomicAdd(&sh[copy + (f2key(x[i]) >> 20)], 1u);
    __syncthreads();
    for (int i = threadIdx.x; i < 4096; i += blockDim.x) {
        unsigned c = sh[i] + sh[4096 + i];
        if (c) atomicAdd(&g_hist1[i], c);
    }
}

// Single-warp cumulative scan over a histogram; finds the bin containing the
// target rank. mode 0: hist1 (target passed in). mode 1: hist2 (target =
// g_rank1). mode 2: hist3, 256 bins (target = g_rank2) -> final threshold.
__global__ void k_scan(int mode, unsigned target0) {
    const unsigned* hist = (mode == 0) ? g_hist1 : (mode == 1) ? g_hist2 : g_hist3;
    const int nbins = (mode == 2) ? 256 : 4096;
    unsigned target = (mode == 0) ? target0 : (mode == 1) ? g_rank1 : g_rank2;
    const int lane = threadIdx.x;
    unsigned run = 0u;
    for (int base = 0; base < nbins; base += 32) {
        unsigned c = hist[base + lane];
        unsigned v = c;
#pragma unroll
        for (int off = 1; off < 32; off <<= 1) {
            unsigned t = __shfl_up_sync(0xffffffffu, v, off);
            if (lane >= off) v += t;
        }
        unsigned incl = run + v;
        unsigned excl = incl - c;
        if (target >= excl && target < incl) {
            if (mode == 0) {
                g_sel1 = (unsigned)(base + lane);
                g_rank1 = target - excl;
            } else if (mode == 1) {
                g_sel2 = (unsigned)(base + lane);
                g_rank2 = target - excl;
            } else {
                unsigned key = (g_sel1 << 20) | (g_sel2 << 8) | (unsigned)(base + lane);
                unsigned u = (key & 0x80000000u) ? (key & 0x7fffffffu) : ~key;
                g_threshold = __uint_as_float(u);
            }
        }
        run += __shfl_sync(0xffffffffu, v, 31);
    }
}

// Pass 2: compact keys matching the selected 12-bit prefix (warp-aggregated
// atomic counter) AND build the next-12-bit histogram in the same pass.
__global__ void k_compact(const float* __restrict__ x, int n) {
    __shared__ unsigned sh[4096];
    for (int i = threadIdx.x; i < 4096; i += blockDim.x) sh[i] = 0u;
    __syncthreads();
    const unsigned sel = g_sel1;
    const int lane = threadIdx.x & 31;
    const float4* x4 = (const float4*)x;
    const int n4 = n >> 2;
    const int stride = gridDim.x * blockDim.x;
    for (int i = blockIdx.x * blockDim.x + threadIdx.x; i < n4; i += stride) {
        float4 v = x4[i];
        float f[4] = {v.x, v.y, v.z, v.w};
#pragma unroll
        for (int c = 0; c < 4; c++) {
            unsigned key = f2key(f[c]);
            bool p = ((key >> 20) == sel);
            unsigned am = __activemask();
            unsigned m = __ballot_sync(am, p);
            if (m) {
                int leader = __ffs(m) - 1;
                unsigned base = 0u;
                if (lane == leader) base = atomicAdd(&g_count, (unsigned)__popc(m));
                base = __shfl_sync(am, base, leader);
                if (p) {
                    unsigned pos = base + (unsigned)__popc(m & ((1u << lane) - 1u));
                    if (pos < CAND_CAP) g_cand[pos] = key;
                    atomicAdd(&sh[(key >> 8) & 0xfffu], 1u);
                }
            }
        }
    }
    for (int i = (n & ~3) + blockIdx.x * blockDim.x + threadIdx.x; i < n; i += stride) {
        unsigned key = f2key(x[i]);
        if ((key >> 20) == sel) {
            unsigned pos = atomicAdd(&g_count, 1u);
            if (pos < CAND_CAP) g_cand[pos] = key;
            atomicAdd(&sh[(key >> 8) & 0xfffu], 1u);
        }
    }
    __syncthreads();
    for (int i = threadIdx.x; i < 4096; i += blockDim.x)
        if (sh[i]) atomicAdd(&g_hist2[i], sh[i]);
}

// Final 8-bit histogram over candidates matching the selected 24-bit prefix
// (candidate array is ~3 MB -> L2 resident, cheap).
__global__ void k_hist3() {
    __shared__ unsigned sh[256];
    if (threadIdx.x < 256) sh[threadIdx.x] = 0u;
    __syncthreads();
    const unsigned nc = min(g_count, CAND_CAP);
    const unsigned sel2 = g_sel2;
    const unsigned stride = gridDim.x * blockDim.x;
    for (unsigned i = blockIdx.x * blockDim.x + threadIdx.x; i < nc; i += stride) {
        unsigned key = g_cand[i];
        if (((key >> 8) & 0xfffu) == sel2) atomicAdd(&sh[key & 0xffu], 1u);
    }
    __syncthreads();
    if (threadIdx.x < 256 && sh[threadIdx.x]) atomicAdd(&g_hist3[threadIdx.x], sh[threadIdx.x]);
}

// Mask pass: out = (x >= threshold) ? 1 : 0
__global__ void k_mask(const float* __restrict__ x, float* __restrict__ out, int n) {
    const float thr = g_threshold;
    const float4* x4 = (const float4*)x;
    float4* o4 = (float4*)out;
    const int n4 = n >> 2;
    const int stride = gridDim.x * blockDim.x;
    for (int i = blockIdx.x * blockDim.x + threadIdx.x; i < n4; i += stride) {
        float4 v = x4[i];
        float4 r;
        r.x = (v.x >= thr) ? 1.0f : 0.0f;
        r.y = (v.y >= thr) ? 1.0f : 0.0f;
        r.z = (v.z >= thr) ? 1.0f : 0.0f;
        r.w = (v.w >= thr) ? 1.0f : 0.0f;
        o4[i] = r;
    }
    for (int i = (n & ~3) + blockIdx.x * blockDim.x + threadIdx.x; i < n; i += stride)
        out[i] = (x[i] >= thr) ? 1.0f : 0.0f;
}

__global__ void k_fill0(float* __restrict__ out, int n) {
    const int stride = gridDim.x * blockDim.x;
    for (int i = blockIdx.x * blockDim.x + threadIdx.x; i < n; i += stride)
        out[i] = 0.0f;
}

extern "C" void kernel_launch(void* const* d_in, const int* in_sizes, int n_in,
                              void* d_out, int out_size) {
    const float* x = (const float*)d_in[0];
    float* out = (float*)d_out;
    const long long n = (long long)in_sizes[0];
    // k = int(n * 0.9) -- matches Python truncation semantics in double precision
    const long long k = (long long)((double)n * 0.9);
    if (k <= 0) {
        k_fill0<<<1184, 256>>>(out, (int)n);
        return;
    }
    const unsigned idx = (unsigned)(n - k);  // 0-indexed ascending rank of threshold

    k_zero<<<16, 256>>>();
    k_hist1<<<592, 512>>>(x, (int)n);      // ~1 wave of 512-thr blocks, 32KB smem
    k_scan<<<1, 32>>>(0, idx);
    k_compact<<<1184, 256>>>(x, (int)n);
    k_scan<<<1, 32>>>(1, 0u);
    k_hist3<<<232, 256>>>();
    k_scan<<<1, 32>>>(2, 0u);
    k_mask<<<1184, 256>>>(x, out, (int)n);
}

// round 2
// speedup vs baseline: 3.4571x; 3.4571x over previous
#include <cuda_runtime.h>

// Top-k threshold mask via sampled radix select.
// Order-preserving key: neg -> ~bits, pos -> bits | 0x80000000 (ascending).

#define CAND_CAP  (1u << 24)
#define STAGE_CAP 6144
#define MARGIN    3000u
#define MAX_EXP   32

static __device__ unsigned g_hist64k[65536];
static __device__ unsigned g_hist2048[2048];
static __device__ unsigned g_hist4096c[4096];
// fallback exact-path hists
static __device__ unsigned g_hist1[4096];
static __device__ unsigned g_hist2[4096];
static __device__ unsigned g_hist3[256];

static __device__ unsigned g_klo, g_khi;     // inclusive key range for candidates
static __device__ unsigned g_below;          // exact count of keys < klo
static __device__ unsigned g_count;          // candidate count
static __device__ unsigned g_overflow;
static __device__ unsigned g_fail;
static __device__ unsigned g_rank;           // target rank within candidates
static __device__ unsigned g_sel20, g_rank20;
static __device__ unsigned g_fsel1, g_frank1, g_fsel2, g_frank2, g_fcount;
static __device__ float    g_threshold;
static __device__ unsigned g_cand[CAND_CAP];

__device__ __forceinline__ unsigned f2key(float f) {
    unsigned u = __float_as_uint(f);
    return (u & 0x80000000u) ? ~u : (u | 0x80000000u);
}
__device__ __forceinline__ float key2f(unsigned key) {
    unsigned u = (key & 0x80000000u) ? (key & 0x7fffffffu) : ~key;
    return __uint_as_float(u);
}

__global__ void k_zero() {
    int t = blockIdx.x * blockDim.x + threadIdx.x;
    int stride = gridDim.x * blockDim.x;
    for (int i = t; i < 65536; i += stride) g_hist64k[i] = 0u;
    if (t < 2048) g_hist2048[t] = 0u;
    if (t < 4096) { g_hist4096c[t] = 0u; g_hist1[t] = 0u; g_hist2[t] = 0u; }
    if (t < 256) g_hist3[t] = 0u;
    if (t == 0) {
        g_below = 0u; g_count = 0u; g_overflow = 0u; g_fail = 0u;
        g_fcount = 0u;
    }
}

// ---------------- sampling ----------------
__global__ void k_sample(const float4* __restrict__ x4, int n4) {
    int s = blockIdx.x * blockDim.x + threadIdx.x;
    long long i = (long long)s * 64;
    if (i < n4) {
        float4 v = x4[i];
        atomicAdd(&g_hist64k[f2key(v.x) >> 16], 1u);
        atomicAdd(&g_hist64k[f2key(v.y) >> 16], 1u);
        atomicAdd(&g_hist64k[f2key(v.z) >> 16], 1u);
        atomicAdd(&g_hist64k[f2key(v.w) >> 16], 1u);
    }
}

// Single block: scan sample histogram, find center bin of target quantile,
// expand by >= MARGIN samples (or MAX_EXP bins) each side -> [g_klo, g_khi].
__global__ void k_pick(unsigned t_target) {
    __shared__ unsigned s_part[1024];
    __shared__ int s_seg;
    __shared__ unsigned s_segexcl;
    int tid = threadIdx.x;
    if (tid == 0) { s_seg = -1; s_segexcl = 0u; }
    unsigned my = 0u;
    for (int b = tid * 64; b < tid * 64 + 64; b++) my += g_hist64k[b];
    s_part[tid] = my;
    __syncthreads();
    for (int off = 1; off < 1024; off <<= 1) {
        unsigned t = (tid >= off) ? s_part[tid - off] : 0u;
        __syncthreads();
        s_part[tid] += t;
        __syncthreads();
    }
    unsigned incl = s_part[tid];
    unsigned excl = incl - my;
    if (my && t_target >= excl && t_target < incl) { s_seg = tid; s_segexcl = excl; }
    __syncthreads();
    if (tid == 0) {
        if (s_seg < 0) { g_klo = 0u; g_khi = 0xffffffffu; return; }
        unsigned cum = s_segexcl;
        int bc = s_seg * 64;
        for (int b = s_seg * 64; b < s_seg * 64 + 64; b++) {
            unsigned c = g_hist64k[b];
            if (t_target >= cum && t_target < cum + c) { bc = b; break; }
            cum += c;
        }
        int lo = bc; unsigned accL = 0u;
        while (lo > 0 && accL < MARGIN && (bc - lo) < MAX_EXP) { lo--; accL += g_hist64k[lo]; }
        int hi = bc; unsigned accR = 0u;
        while (hi < 65535 && accR < MARGIN && (hi - bc) < MAX_EXP) { hi++; accR += g_hist64k[hi]; }
        g_klo = (unsigned)lo << 16;
        g_khi = ((unsigned)hi << 16) | 0xffffu;
    }
}

// ---------------- main fused pass: exact below-count + candidate compaction ----
__global__ void k_main(const float4* __restrict__ x4, int n4,
                       const float* __restrict__ x, int n) {
    __shared__ unsigned s_buf[STAGE_CAP];
    __shared__ unsigned s_cnt, s_below, s_base;
    if (threadIdx.x == 0) { s_cnt = 0u; s_below = 0u; }
    __syncthreads();
    const unsigned klo = g_klo, khi = g_khi;
    const int lane = threadIdx.x & 31;
    const int stride = gridDim.x * blockDim.x;
    unsigned below = 0u;
    for (int i = blockIdx.x * blockDim.x + threadIdx.x; i < n4; i += stride) {
        float4 v = x4[i];
        unsigned k0 = f2key(v.x), k1 = f2key(v.y), k2 = f2key(v.z), k3 = f2key(v.w);
        below += (k0 < klo) + (k1 < klo) + (k2 < klo) + (k3 < klo);
        if (k0 >= klo && k0 <= khi) { unsigned p = atomicAdd(&s_cnt, 1u); if (p < STAGE_CAP) s_buf[p] = k0; }
        if (k1 >= klo && k1 <= khi) { unsigned p = atomicAdd(&s_cnt, 1u); if (p < STAGE_CAP) s_buf[p] = k1; }
        if (k2 >= klo && k2 <= khi) { unsigned p = atomicAdd(&s_cnt, 1u); if (p < STAGE_CAP) s_buf[p] = k2; }
        if (k3 >= klo && k3 <= khi) { unsigned p = atomicAdd(&s_cnt, 1u); if (p < STAGE_CAP) s_buf[p] = k3; }
    }
    for (int i = (n & ~3) + blockIdx.x * blockDim.x + threadIdx.x; i < n; i += stride) {
        unsigned k0 = f2key(x[i]);
        below += (k0 < klo);
        if (k0 >= klo && k0 <= khi) { unsigned p = atomicAdd(&s_cnt, 1u); if (p < STAGE_CAP) s_buf[p] = k0; }
    }
#pragma unroll
    for (int off = 16; off > 0; off >>= 1)
        below += __shfl_down_sync(0xffffffffu, below, off);
    if (lane == 0) atomicAdd(&s_below, below);
    __syncthreads();
    unsigned cnt = s_cnt < STAGE_CAP ? s_cnt : STAGE_CAP;
    if (threadIdx.x == 0) {
        if (s_cnt > STAGE_CAP) atomicExch(&g_overflow, 1u);
        atomicAdd(&g_below, s_below);
        s_base = atomicAdd(&g_count, cnt);
    }
    __syncthreads();
    unsigned base = s_base;
    for (unsigned i = threadIdx.x; i < cnt; i += blockDim.x) g_cand[base + i] = s_buf[i];
}

__global__ void k_check(unsigned idx) {
    if (threadIdx.x == 0 && blockIdx.x == 0) {
        unsigned below = g_below, nc = g_count;
        if (g_overflow || idx < below || (idx - below) >= nc || nc > CAND_CAP)
            g_fail = 1u;
        else
            g_rank = idx - below;
    }
}

// ---------------- candidate select (L2-resident) ----------------
__global__ void k_chist(void) {
    if (g_fail) return;
    __shared__ unsigned sh[2048];
    for (int i = threadIdx.x; i < 2048; i += blockDim.x) sh[i] = 0u;
    __syncthreads();
    const unsigned base12 = g_klo >> 12;
    const unsigned nc = g_count;
    const unsigned stride = gridDim.x * blockDim.x;
    for (unsigned i = blockIdx.x * blockDim.x + threadIdx.x; i < nc; i += stride) {
        unsigned b = (g_cand[i] >> 12) - base12;
        if (b < 2048u) atomicAdd(&sh[b], 1u);
        else atomicExch(&g_fail, 1u);
    }
    __syncthreads();
    for (int i = threadIdx.x; i < 2048; i += blockDim.x)
        if (sh[i]) atomicAdd(&g_hist2048[i], sh[i]);
}

__device__ __forceinline__ void warp_select(const unsigned* hist, int nbins,
                                            unsigned target, unsigned* out_bin,
                                            unsigned* out_rank) {
    int lane = threadIdx.x & 31;
    unsigned run = 0u;
    for (int base = 0; base < nbins; base += 32) {
        unsigned c = hist[base + lane];
        unsigned v = c;
#pragma unroll
        for (int off = 1; off < 32; off <<= 1) {
            unsigned t = __shfl_up_sync(0xffffffffu, v, off);
            if (lane >= off) v += t;
        }
        unsigned incl = run + v, excl = incl - c;
        if (c && target >= excl && target < incl) { *out_bin = (unsigned)(base + lane); *out_rank = target - excl; }
        run += __shfl_sync(0xffffffffu, v, 31);
    }
}

__global__ void k_scan2048(void) {
    if (g_fail) return;
    unsigned bin = 0u, r = 0u;
    __shared__ unsigned s_bin, s_r;
    if (threadIdx.x == 0) { s_bin = 0xffffffffu; s_r = 0u; }
    __syncwarp();
    warp_select(g_hist2048, 2048, g_rank, &s_bin, &s_r);
    __syncwarp();
    bin = s_bin; r = s_r;
    if (threadIdx.x == 0) {
        if (bin == 0xffffffffu) { g_fail = 1u; return; }
        g_sel20 = (g_klo >> 12) + bin;
        g_rank20 = r;
    }
}

__global__ void k_chist2(void) {
    if (g_fail) return;
    __shared__ unsigned sh[4096];
    for (int i = threadIdx.x; i < 4096; i += blockDim.x) sh[i] = 0u;
    __syncthreads();
    const unsigned sel = g_sel20;
    const unsigned nc = g_count;
    const unsigned stride = gridDim.x * blockDim.x;
    for (unsigned i = blockIdx.x * blockDim.x + threadIdx.x; i < nc; i += stride) {
        unsigned key = g_cand[i];
        if ((key >> 12) == sel) atomicAdd(&sh[key & 0xfffu], 1u);
    }
    __syncthreads();
    for (int i = threadIdx.x; i < 4096; i += blockDim.x)
        if (sh[i]) atomicAdd(&g_hist4096c[i], sh[i]);
}

__global__ void k_scan4096c(void) {
    if (g_fail) return;
    __shared__ unsigned s_bin, s_r;
    if (threadIdx.x == 0) { s_bin = 0xffffffffu; s_r = 0u; }
    __syncwarp();
    warp_select(g_hist4096c, 4096, g_rank20, &s_bin, &s_r);
    __syncwarp();
    if (threadIdx.x == 0) {
        if (s_bin == 0xffffffffu) { g_fail = 1u; return; }
        g_threshold = key2f((g_sel20 << 12) | s_bin);
    }
}

// ---------------- fallback exact radix path (gated on g_fail) ----------------
__global__ void k_fhist1(const float* __restrict__ x, int n) {
    if (!g_fail) return;
    __shared__ unsigned sh[2 * 4096];
    for (int i = threadIdx.x; i < 2 * 4096; i += blockDim.x) sh[i] = 0u;
    __syncthreads();
    const unsigned copy = ((threadIdx.x >> 5) & 1u) * 4096u;
    const float4* x4 = (const float4*)x;
    const int n4 = n >> 2;
    const int stride = gridDim.x * blockDim.x;
    for (int i = blockIdx.x * blockDim.x + threadIdx.x; i < n4; i += stride) {
        float4 v = x4[i];
        atomicAdd(&sh[copy + (f2key(v.x) >> 20)], 1u);
        atomicAdd(&sh[copy + (f2key(v.y) >> 20)], 1u);
        atomicAdd(&sh[copy + (f2key(v.z) >> 20)], 1u);
        atomicAdd(&sh[copy + (f2key(v.w) >> 20)], 1u);
    }
    for (int i = (n & ~3) + blockIdx.x * blockDim.x + threadIdx.x; i < n; i += stride)
        atomicAdd(&sh[copy + (f2key(x[i]) >> 20)], 1u);
    __syncthreads();
    for (int i = threadIdx.x; i < 4096; i += blockDim.x) {
        unsigned c = sh[i] + sh[4096 + i];
        if (c) atomicAdd(&g_hist1[i], c);
    }
}

__global__ void k_fscan(int mode, unsigned target0) {
    if (!g_fail) return;
    const unsigned* hist = (mode == 0) ? g_hist1 : (mode == 1) ? g_hist2 : g_hist3;
    const int nbins = (mode == 2) ? 256 : 4096;
    unsigned target = (mode == 0) ? target0 : (mode == 1) ? g_frank1 : g_frank2;
    __shared__ unsigned s_bin, s_r;
    if (threadIdx.x == 0) { s_bin = 0xffffffffu; s_r = 0u; }
    __syncwarp();
    warp_select(hist, nbins, target, &s_bin, &s_r);
    __syncwarp();
    if (threadIdx.x == 0 && s_bin != 0xffffffffu) {
        if (mode == 0) { g_fsel1 = s_bin; g_frank1 = s_r; }
        else if (mode == 1) { g_fsel2 = s_bin; g_frank2 = s_r; }
        else g_threshold = key2f((g_fsel1 << 20) | (g_fsel2 << 8) | s_bin);
    }
}

__global__ void k_fcompact(const float* __restrict__ x, int n) {
    if (!g_fail) return;
    __shared__ unsigned sh[4096];
    __shared__ unsigned s_buf[STAGE_CAP];
    __shared__ unsigned s_cnt, s_base;
    for (int i = threadIdx.x; i < 4096; i += blockDim.x) sh[i] = 0u;
    if (threadIdx.x == 0) s_cnt = 0u;
    __syncthreads();
    const unsigned sel = g_fsel1;
    const int stride = gridDim.x * blockDim.x;
    for (int i = blockIdx.x * blockDim.x + threadIdx.x; i < n; i += stride) {
        unsigned key = f2key(x[i]);
        if ((key >> 20) == sel) {
            unsigned p = atomicAdd(&s_cnt, 1u);
            if (p < STAGE_CAP) s_buf[p] = key;
            atomicAdd(&sh[(key >> 8) & 0xfffu], 1u);
        }
    }
    __syncthreads();
    unsigned cnt = s_cnt < STAGE_CAP ? s_cnt : STAGE_CAP;
    if (threadIdx.x == 0) s_base = atomicAdd(&g_fcount, cnt);
    __syncthreads();
    unsigned base = s_base;
    for (unsigned i = threadIdx.x; i < cnt; i += blockDim.x)
        if (base + i < CAND_CAP) g_cand[base + i] = s_buf[i];
    for (int i = threadIdx.x; i < 4096; i += blockDim.x)
        if (sh[i]) atomicAdd(&g_hist2[i], sh[i]);
}

__global__ void k_fhist3(void) {
    if (!g_fail) return;
    __shared__ unsigned sh[256];
    if (threadIdx.x < 256) sh[threadIdx.x] = 0u;
    __syncthreads();
    const unsigned nc = g_fcount < CAND_CAP ? g_fcount : CAND_CAP;
    const unsigned sel2 = g_fsel2;
    const unsigned stride = gridDim.x * blockDim.x;
    for (unsigned i = blockIdx.x * blockDim.x + threadIdx.x; i < nc; i += stride) {
        unsigned key = g_cand[i];
        if (((key >> 8) & 0xfffu) == sel2) atomicAdd(&sh[key & 0xffu], 1u);
    }
    __syncthreads();
    if (threadIdx.x < 256 && sh[threadIdx.x]) atomicAdd(&g_hist3[threadIdx.x], sh[threadIdx.x]);
}

// ---------------- mask ----------------
__global__ void k_mask(const float* __restrict__ x, float* __restrict__ out, int n) {
    const float thr = g_threshold;
    const float4* x4 = (const float4*)x;
    float4* o4 = (float4*)out;
    const int n4 = n >> 2;
    const int stride = gridDim.x * blockDim.x;
    for (int i = blockIdx.x * blockDim.x + threadIdx.x; i < n4; i += stride) {
        float4 v = x4[i];
        float4 r;
        r.x = (v.x >= thr) ? 1.0f : 0.0f;
        r.y = (v.y >= thr) ? 1.0f : 0.0f;
        r.z = (v.z >= thr) ? 1.0f : 0.0f;
        r.w = (v.w >= thr) ? 1.0f : 0.0f;
        o4[i] = r;
    }
    for (int i = (n & ~3) + blockIdx.x * blockDim.x + threadIdx.x; i < n; i += stride)
        out[i] = (x[i] >= thr) ? 1.0f : 0.0f;
}

__global__ void k_fill0(float* __restrict__ out, int n) {
    const int stride = gridDim.x * blockDim.x;
    for (int i = blockIdx.x * blockDim.x + threadIdx.x; i < n; i += stride)
        out[i] = 0.0f;
}

extern "C" void kernel_launch(void* const* d_in, const int* in_sizes, int n_in,
                              void* d_out, int out_size) {
    const float* x = (const float*)d_in[0];
    float* out = (float*)d_out;
    const long long n = (long long)in_sizes[0];
    const long long k = (long long)((double)n * 0.9);
    if (k <= 0) { k_fill0<<<1184, 256>>>(out, (int)n); return; }
    const unsigned idx = (unsigned)(n - k);   // 0-indexed ascending rank of threshold
    const int n4 = (int)(n >> 2);
    const long long s_n4 = (n4 + 63) / 64;          // sampled float4 count
    const long long m = s_n4 * 4;                   // sampled float count
    unsigned t_target = (unsigned)((double)idx * (double)m / (double)n);
    if (t_target >= (unsigned)m) t_target = (unsigned)m - 1u;

    k_zero<<<320, 256>>>();
    k_sample<<<(unsigned)((s_n4 + 255) / 256), 256>>>((const float4*)x, n4);
    k_pick<<<1, 1024>>>(t_target);
    k_main<<<1184, 256>>>((const float4*)x, n4, x, (int)n);
    k_check<<<1, 32>>>(idx);
    k_chist<<<232, 256>>>();
    k_scan2048<<<1, 32>>>();
    k_chist2<<<232, 256>>>();
    k_scan4096c<<<1, 32>>>();
    // fallback exact path (no-ops unless g_fail)
    k_fhist1<<<592, 512>>>(x, (int)n);
    k_fscan<<<1, 32>>>(0, idx);
    k_fcompact<<<1184, 256>>>(x, (int)n);
    k_fscan<<<1, 32>>>(1, 0u);
    k_fhist3<<<232, 256>>>();
    k_fscan<<<1, 32>>>(2, 0u);
    k_mask<<<1184, 256>>>(x, out, (int)n);
}

// round 3
// speedup vs baseline: 4.3342x; 1.2537x over previous
#include <cuda_runtime.h>

// Top-k threshold mask via sampled radix select, with mask fused into the
// main pass (only interval candidates get fixed up after the exact threshold
// is known). Order-preserving key: neg -> ~bits, pos -> bits|0x80000000.

#define CAND_CAP  (1u << 24)
#define STAGE_CAP 2048
#define MARGIN    3000u
#define MAX_EXP   15

static __device__ unsigned g_hist64k[65536];   // sample hist / fallback hist
static __device__ unsigned g_hist2048[2048];   // level-1 and level-2 candidate hist

static __device__ unsigned g_klo, g_khi, g_shift;
static __device__ unsigned g_below;            // exact count of keys < klo
static __device__ unsigned g_count;            // candidate count
static __device__ unsigned g_overflow;
static __device__ unsigned g_fail;
static __device__ unsigned g_b2base, g_rank2;  // level-2 base key + rank
static __device__ unsigned g_fb, g_fr;         // fallback bin + rank
static __device__ float    g_threshold;
static __device__ unsigned g_cand[CAND_CAP];
static __device__ unsigned g_cidx[CAND_CAP];

__device__ __forceinline__ unsigned f2key(float f) {
    unsigned u = __float_as_uint(f);
    return (u & 0x80000000u) ? ~u : (u | 0x80000000u);
}
__device__ __forceinline__ float key2f(unsigned key) {
    unsigned u = (key & 0x80000000u) ? (key & 0x7fffffffu) : ~key;
    return __uint_as_float(u);
}

// ---------------- sampling (1/64 of float4s, 4 values each) ----------------
__global__ void k_sample(const float4* __restrict__ x4, int n4) {
    long long i = (long long)(blockIdx.x * blockDim.x + threadIdx.x) * 64;
    if (i < n4) {
        float4 v = __ldg(&x4[i]);
        atomicAdd(&g_hist64k[f2key(v.x) >> 16], 1u);
        atomicAdd(&g_hist64k[f2key(v.y) >> 16], 1u);
        atomicAdd(&g_hist64k[f2key(v.z) >> 16], 1u);
        atomicAdd(&g_hist64k[f2key(v.w) >> 16], 1u);
    }
}

// Single block: find target quantile bin of the sample hist, expand by MARGIN
// samples (bounded by MAX_EXP bins) per side, derive shift. Also zeroes the
// sample hist and all per-replay counters.
__global__ void k_pick(unsigned t_target) {
    __shared__ unsigned s_part[1024];
    __shared__ int s_seg;
    __shared__ unsigned s_segexcl;
    int tid = threadIdx.x;
    if (tid == 0) s_seg = -1;
    if (tid == 1) { g_below = 0u; g_count = 0u; g_overflow = 0u; g_fail = 0u; }
    unsigned my = 0u;
    for (int b = tid * 64; b < tid * 64 + 64; b++) my += g_hist64k[b];
    s_part[tid] = my;
    __syncthreads();
    for (int off = 1; off < 1024; off <<= 1) {
        unsigned t = (tid >= off) ? s_part[tid - off] : 0u;
        __syncthreads();
        s_part[tid] += t;
        __syncthreads();
    }
    unsigned incl = s_part[tid], excl = incl - my;
    if (my && t_target >= excl && t_target < incl) { s_seg = tid; s_segexcl = excl; }
    __syncthreads();
    if (tid == 0) {
        if (s_seg < 0) {
            g_fail = 1u; g_klo = 1u; g_khi = 0u; g_shift = 0u;
        } else {
            unsigned cum = s_segexcl;
            int bc = s_seg * 64;
            for (int b = s_seg * 64; b < s_seg * 64 + 64; b++) {
                unsigned c = g_hist64k[b];
                if (t_target >= cum && t_target < cum + c) { bc = b; break; }
                cum += c;
            }
            int lo = bc; unsigned accL = 0u;
            while (lo > 0 && accL < MARGIN && (bc - lo) < MAX_EXP) { lo--; accL += g_hist64k[lo]; }
            int hi = bc; unsigned accR = 0u;
            while (hi < 65535 && accR < MARGIN && (hi - bc) < MAX_EXP) { hi++; accR += g_hist64k[hi]; }
            if (lo == 0x8000) lo--;   // keep -0.0 inside the candidate interval
            unsigned klo = (unsigned)lo << 16;
            unsigned khi = ((unsigned)hi << 16) | 0xffffu;
            unsigned range = khi - klo, sh = 0u;
            while ((range >> sh) >= 2048u) sh++;
            g_klo = klo; g_khi = khi; g_shift = sh;
        }
    }
    __syncthreads();  // thread 0 done reading g_hist64k
    for (int b = tid; b < 65536; b += 1024) g_hist64k[b] = 0u;
}

// ---------------- main fused pass ----------------
// Reads x once, writes provisional mask (key > khi), counts keys < klo,
// stages (key, index) for interval candidates, builds level-1 candidate hist.
__global__ void k_main(const float4* __restrict__ x4, int n4,
                       float* __restrict__ out) {
    __shared__ unsigned s_key[STAGE_CAP];
    __shared__ unsigned s_idx[STAGE_CAP];
    __shared__ unsigned s_hist[2048];
    __shared__ unsigned s_cnt, s_below, s_base;
    for (int i = threadIdx.x; i < 2048; i += blockDim.x) s_hist[i] = 0u;
    if (threadIdx.x == 0) { s_cnt = 0u; s_below = 0u; }
    __syncthreads();
    const unsigned klo = g_klo, khi = g_khi, sh = g_shift;
    const int lane = threadIdx.x & 31;
    const int stride = gridDim.x * blockDim.x;
    float4* o4 = (float4*)out;
    unsigned below = 0u;
#pragma unroll 4
    for (int i = blockIdx.x * blockDim.x + threadIdx.x; i < n4; i += stride) {
        float4 v = __ldcs(&x4[i]);
        unsigned k0 = f2key(v.x), k1 = f2key(v.y), k2 = f2key(v.z), k3 = f2key(v.w);
        float4 r;
        r.x = (k0 > khi) ? 1.0f : 0.0f;
        r.y = (k1 > khi) ? 1.0f : 0.0f;
        r.z = (k2 > khi) ? 1.0f : 0.0f;
        r.w = (k3 > khi) ? 1.0f : 0.0f;
        __stcs(&o4[i], r);
        below += (k0 < klo) + (k1 < klo) + (k2 < klo) + (k3 < klo);
        unsigned e = (unsigned)i * 4u;
        if (k0 >= klo && k0 <= khi) {
            unsigned p = atomicAdd(&s_cnt, 1u);
            if (p < STAGE_CAP) { s_key[p] = k0; s_idx[p] = e; atomicAdd(&s_hist[(k0 - klo) >> sh], 1u); }
        }
        if (k1 >= klo && k1 <= khi) {
            unsigned p = atomicAdd(&s_cnt, 1u);
            if (p < STAGE_CAP) { s_key[p] = k1; s_idx[p] = e + 1u; atomicAdd(&s_hist[(k1 - klo) >> sh], 1u); }
        }
        if (k2 >= klo && k2 <= khi) {
            unsigned p = atomicAdd(&s_cnt, 1u);
            if (p < STAGE_CAP) { s_key[p] = k2; s_idx[p] = e + 2u; atomicAdd(&s_hist[(k2 - klo) >> sh], 1u); }
        }
        if (k3 >= klo && k3 <= khi) {
            unsigned p = atomicAdd(&s_cnt, 1u);
            if (p < STAGE_CAP) { s_key[p] = k3; s_idx[p] = e + 3u; atomicAdd(&s_hist[(k3 - klo) >> sh], 1u); }
        }
    }
#pragma unroll
    for (int off = 16; off > 0; off >>= 1)
        below += __shfl_down_sync(0xffffffffu, below, off);
    if (lane == 0) atomicAdd(&s_below, below);
    __syncthreads();
    unsigned cnt = s_cnt < STAGE_CAP ? s_cnt : STAGE_CAP;
    if (threadIdx.x == 0) {
        if (s_cnt > STAGE_CAP) atomicExch(&g_overflow, 1u);
        atomicAdd(&g_below, s_below);
        s_base = atomicAdd(&g_count, cnt);
    }
    __syncthreads();
    unsigned base = s_base;
    for (unsigned i = threadIdx.x; i < cnt; i += blockDim.x) {
        g_cand[base + i] = s_key[i];
        g_cidx[base + i] = s_idx[i];
    }
    for (int i = threadIdx.x; i < 2048; i += blockDim.x)
        if (s_hist[i]) atomicAdd(&g_hist2048[i], s_hist[i]);
}

// ---------------- selection scans ----------------
__device__ __forceinline__ void warp_select(const unsigned* hist, int nbins,
                                            unsigned target, unsigned* out_bin,
                                            unsigned* out_rank) {
    int lane = threadIdx.x & 31;
    unsigned run = 0u;
    for (int base = 0; base < nbins; base += 32) {
        unsigned c = hist[base + lane];
        unsigned v = c;
#pragma unroll
        for (int off = 1; off < 32; off <<= 1) {
            unsigned t = __shfl_up_sync(0xffffffffu, v, off);
            if (lane >= off) v += t;
        }
        unsigned incl = run + v, excl = incl - c;
        if (c && target >= excl && target < incl) { *out_bin = (unsigned)(base + lane); *out_rank = target - excl; }
        run += __shfl_sync(0xffffffffu, v, 31);
    }
}

// Validity check + level-1 scan. Always re-zeroes g_hist2048 afterwards.
__global__ void k_scan1(unsigned idx) {
    __shared__ unsigned s_bin, s_rank, s_target, s_ok;
    int tid = threadIdx.x;
    if (tid == 0) {
        unsigned below = g_below, cnt = g_count;
        unsigned ok = (!g_overflow) && (!g_fail) && (idx >= below) &&
                      ((idx - below) < cnt) && (cnt <= CAND_CAP);
        if (!ok) g_fail = 1u;
        s_ok = ok; s_target = idx - below; s_bin = 0xffffffffu; s_rank = 0u;
    }
    __syncthreads();
    if (s_ok && tid < 32) warp_select(g_hist2048, 2048, s_target, &s_bin, &s_rank);
    __syncthreads();
    if (tid == 0 && s_ok) {
        if (s_bin == 0xffffffffu) g_fail = 1u;
        else { g_b2base = g_klo + (s_bin << g_shift); g_rank2 = s_rank; }
    }
    __syncthreads();
    for (int i = tid; i < 2048; i += blockDim.x) g_hist2048[i] = 0u;
}

// Level-2 candidate hist: exact per-key bins within selected level-1 bin.
__global__ void k_sel2(void) {
    if (g_fail) return;
    __shared__ unsigned sh[2048];
    for (int i = threadIdx.x; i < 2048; i += blockDim.x) sh[i] = 0u;
    __syncthreads();
    const unsigned b2 = g_b2base;
    const unsigned w = 1u << g_shift;
    const unsigned nc = g_count;
    const unsigned stride = gridDim.x * blockDim.x;
    for (unsigned i = blockIdx.x * blockDim.x + threadIdx.x; i < nc; i += stride) {
        unsigned off = g_cand[i] - b2;
        if (off < w) atomicAdd(&sh[off], 1u);
    }
    __syncthreads();
    for (int i = threadIdx.x; i < 2048; i += blockDim.x)
        if (sh[i]) atomicAdd(&g_hist2048[i], sh[i]);
}

__global__ void k_scan2(void) {
    __shared__ unsigned s_bin, s_rank;
    int tid = threadIdx.x;
    unsigned fail = g_fail;
    if (tid == 0) { s_bin = 0xffffffffu; s_rank = 0u; }
    __syncthreads();
    if (!fail && tid < 32) {
        int nbins = (int)(1u << g_shift);
        warp_select(g_hist2048, nbins < 32 ? 32 : nbins, g_rank2, &s_bin, &s_rank);
    }
    __syncthreads();
    if (tid == 0 && !fail) {
        if (s_bin == 0xffffffffu) g_fail = 1u;
        else g_threshold = key2f(g_b2base + s_bin);
    }
    __syncthreads();
    for (int i = tid; i < 2048; i += blockDim.x) g_hist2048[i] = 0u;
}

// Fixup: set mask=1 for candidates at/above threshold (others already 0).
__global__ void k_fixup(float* __restrict__ out) {
    if (g_fail) return;
    const float thr = g_threshold;
    const unsigned nc = g_count;
    const unsigned stride = gridDim.x * blockDim.x;
    for (unsigned i = blockIdx.x * blockDim.x + threadIdx.x; i < nc; i += stride) {
        if (key2f(g_cand[i]) >= thr) out[g_cidx[i]] = 1.0f;
    }
}

// ---------------- fallback exact two-pass 16-bit radix (gated) ----------------
__global__ void f_hist(const float* __restrict__ x, int n, int mode) {
    if (!g_fail) return;
    const unsigned fb = g_fb;
    const int stride = gridDim.x * blockDim.x;
    for (int i = blockIdx.x * blockDim.x + threadIdx.x; i < n; i += stride) {
        unsigned key = f2key(x[i]);
        if (mode == 0) atomicAdd(&g_hist64k[key >> 16], 1u);
        else if ((key >> 16) == fb) atomicAdd(&g_hist64k[key & 0xffffu], 1u);
    }
}

__global__ void f_scan(int mode, unsigned idx) {
    if (!g_fail) return;
    __shared__ unsigned s_part[1024];
    __shared__ int s_seg;
    __shared__ unsigned s_segexcl;
    int tid = threadIdx.x;
    unsigned target = (mode == 0) ? idx : g_fr;
    if (tid == 0) s_seg = -1;
    unsigned my = 0u;
    for (int b = tid * 64; b < tid * 64 + 64; b++) my += g_hist64k[b];
    s_part[tid] = my;
    __syncthreads();
    for (int off = 1; off < 1024; off <<= 1) {
        unsigned t = (tid >= off) ? s_part[tid - off] : 0u;
        __syncthreads();
        s_part[tid] += t;
        __syncthreads();
    }
    unsigned incl = s_part[tid], excl = incl - my;
    if (my && target >= excl && target < incl) { s_seg = tid; s_segexcl = excl; }
    __syncthreads();
    if (tid == 0 && s_seg >= 0) {
        unsigned cum = s_segexcl;
        for (int b = s_seg * 64; b < s_seg * 64 + 64; b++) {
            unsigned c = g_hist64k[b];
            if (target >= cum && target < cum + c) {
                if (mode == 0) { g_fb = (unsigned)b; g_fr = target - cum; }
                else g_threshold = key2f((g_fb << 16) | (unsigned)b);
                break;
            }
            cum += c;
        }
    }
    __syncthreads();
    for (int b = tid; b < 65536; b += 1024) g_hist64k[b] = 0u;
}

__global__ void f_mask(const float* __restrict__ x, float* __restrict__ out, int n) {
    if (!g_fail) return;
    const float thr = g_threshold;
    const float4* x4 = (const float4*)x;
    float4* o4 = (float4*)out;
    const int n4 = n >> 2;
    const int stride = gridDim.x * blockDim.x;
    for (int i = blockIdx.x * blockDim.x + threadIdx.x; i < n4; i += stride) {
        float4 v = x4[i];
        float4 r;
        r.x = (v.x >= thr) ? 1.0f : 0.0f;
        r.y = (v.y >= thr) ? 1.0f : 0.0f;
        r.z = (v.z >= thr) ? 1.0f : 0.0f;
        r.w = (v.w >= thr) ? 1.0f : 0.0f;
        o4[i] = r;
    }
    for (int i = (n & ~3) + blockIdx.x * blockDim.x + threadIdx.x; i < n; i += stride)
        out[i] = (x[i] >= thr) ? 1.0f : 0.0f;
}

// tail elements (n not multiple of 4) handled by scalar main path
__global__ void k_main_tail(const float* __restrict__ x, int n,
                            float* __restrict__ out) {
    int start = n & ~3;
    int i = start + blockIdx.x * blockDim.x + threadIdx.x;
    if (i < n) {
        unsigned key = f2key(x[i]);
        out[i] = (key > g_khi) ? 1.0f : 0.0f;
        if (key < g_klo) atomicAdd(&g_below, 1u);
        else if (key <= g_khi) {
            unsigned p = atomicAdd(&g_count, 1u);
            if (p < CAND_CAP) {
                g_cand[p] = key; g_cidx[p] = (unsigned)i;
                atomicAdd(&g_hist2048[(key - g_klo) >> g_shift], 1u);
            } else atomicExch(&g_overflow, 1u);
        }
    }
}

__global__ void k_fill0(float* __restrict__ out, int n) {
    const int stride = gridDim.x * blockDim.x;
    for (int i = blockIdx.x * blockDim.x + threadIdx.x; i < n; i += stride)
        out[i] = 0.0f;
}

extern "C" void kernel_launch(void* const* d_in, const int* in_sizes, int n_in,
                              void* d_out, int out_size) {
    const float* x = (const float*)d_in[0];
    float* out = (float*)d_out;
    const long long n = (long long)in_sizes[0];
    const long long k = (long long)((double)n * 0.9);
    if (k <= 0) { k_fill0<<<1184, 256>>>(out, (int)n); return; }
    const unsigned idx = (unsigned)(n - k);   // 0-indexed ascending rank
    const int n4 = (int)(n >> 2);
    const long long s_n4 = (n4 + 63) / 64;
    const long long m = s_n4 * 4;
    unsigned t_target = (unsigned)((double)idx * (double)m / (double)n);
    if (t_target >= (unsigned)m) t_target = (unsigned)m - 1u;

    k_sample<<<(unsigned)((s_n4 + 255) / 256), 256>>>((const float4*)x, n4);
    k_pick<<<1, 1024>>>(t_target);
    k_main<<<1184, 256>>>((const float4*)x, n4, out);
    if (n & 3) k_main_tail<<<1, 64>>>(x, (int)n, out);
    k_scan1<<<1, 1024>>>(idx);
    k_sel2<<<232, 256>>>();
    k_scan2<<<1, 1024>>>();
    k_fixup<<<232, 256>>>(out);
    // fallback exact path (no-ops unless g_fail)
    f_hist<<<232, 256>>>(x, (int)n, 0);
    f_scan<<<1, 1024>>>(0, idx);
    f_hist<<<232, 256>>>(x, (int)n, 1);
    f_scan<<<1, 1024>>>(1, idx);
    f_mask<<<592, 256>>>(x, out, (int)n);
}